// round 1
// baseline (speedup 1.0000x reference)
#include <cuda_runtime.h>
#include <cuda_bf16.h>

#define N_CLASSES 9
#define N_GROUPS  2
#define N_BINS    (N_CLASSES * N_GROUPS)   // 18
#define WARPS_PER_BLOCK 8
#define THREADS_PER_BLOCK (WARPS_PER_BLOCK * 32)

// Global scratch for the 18-bin histogram (no allocations allowed).
__device__ unsigned int g_counts[N_BINS];

__global__ void zero_counts_kernel() {
    if (threadIdx.x < N_BINS) g_counts[threadIdx.x] = 0u;
}

// Per-lane privatized shared-memory histogram:
//   hist[warp][bin*32 + lane]  -> bank index == lane  => conflict-free,
//   and each lane exclusively owns its column => NO atomics in hot loop.
__global__ void __launch_bounds__(THREADS_PER_BLOCK)
hist_kernel(const int* __restrict__ preds,
            const int* __restrict__ attrs,
            int n, int n4)
{
    __shared__ unsigned int hist[WARPS_PER_BLOCK][N_BINS * 32];
    __shared__ unsigned int blk[N_BINS];

    // Zero shared
    for (int i = threadIdx.x; i < WARPS_PER_BLOCK * N_BINS * 32; i += THREADS_PER_BLOCK)
        (&hist[0][0])[i] = 0u;
    if (threadIdx.x < N_BINS) blk[threadIdx.x] = 0u;
    __syncthreads();

    const int warp = threadIdx.x >> 5;
    const int lane = threadIdx.x & 31;
    unsigned int* h = &hist[warp][lane];   // lane-offset base; index by bin*32

    const int4* __restrict__ p4 = (const int4*)preds;
    const int4* __restrict__ a4 = (const int4*)attrs;

    const int tid    = blockIdx.x * THREADS_PER_BLOCK + threadIdx.x;
    const int stride = gridDim.x * THREADS_PER_BLOCK;

    for (int i = tid; i < n4; i += stride) {
        int4 p = p4[i];
        int4 a = a4[i];
        int b0 = p.x * N_GROUPS + a.x;
        int b1 = p.y * N_GROUPS + a.y;
        int b2 = p.z * N_GROUPS + a.z;
        int b3 = p.w * N_GROUPS + a.w;
        h[b0 * 32] += 1u;
        h[b1 * 32] += 1u;
        h[b2 * 32] += 1u;
        h[b3 * 32] += 1u;
    }

    // Scalar tail (n not multiple of 4) — handled by block 0 only.
    if (blockIdx.x == 0) {
        for (int i = n4 * 4 + threadIdx.x; i < n; i += THREADS_PER_BLOCK) {
            int b = preds[i] * N_GROUPS + attrs[i];
            h[b * 32] += 1u;
        }
    }
    __syncthreads();

    // Reduce 8 warps x 576 counters -> 18 block totals
    for (int idx = threadIdx.x; idx < N_BINS * 32; idx += THREADS_PER_BLOCK) {
        unsigned int s = 0;
        #pragma unroll
        for (int w = 0; w < WARPS_PER_BLOCK; w++) s += hist[w][idx];
        atomicAdd(&blk[idx >> 5], s);
    }
    __syncthreads();

    if (threadIdx.x < N_BINS)
        atomicAdd(&g_counts[threadIdx.x], blk[threadIdx.x]);
}

__global__ void finalize_kernel(float* __restrict__ out, float n_total) {
    if (threadIdx.x == 0) {
        float c[N_BINS];
        #pragma unroll
        for (int i = 0; i < N_BINS; i++) c[i] = (float)g_counts[i];

        float n1 = 0.0f;
        #pragma unroll
        for (int b = 0; b < N_CLASSES; b++) n1 += c[2 * b + 1];
        float n0 = n_total - n1;

        float s = 0.0f;
        #pragma unroll
        for (int b = 0; b < N_CLASSES; b++) {
            float d = c[2 * b] / n0 - c[2 * b + 1] / n1;
            s += d * d;
        }
        out[0] = s;
    }
}

extern "C" void kernel_launch(void* const* d_in, const int* in_sizes, int n_in,
                              void* d_out, int out_size)
{
    const int* preds = (const int*)d_in[0];
    const int* attrs = (const int*)d_in[1];
    float* out = (float*)d_out;
    int n  = in_sizes[0];
    int n4 = n >> 2;

    int blocks = (n4 + THREADS_PER_BLOCK - 1) / THREADS_PER_BLOCK;
    const int max_blocks = 148 * 8;   // ~8 waves of CTAs, grid-stride covers rest
    if (blocks > max_blocks) blocks = max_blocks;
    if (blocks < 1) blocks = 1;

    zero_counts_kernel<<<1, 32>>>();
    hist_kernel<<<blocks, THREADS_PER_BLOCK>>>(preds, attrs, n, n4);
    finalize_kernel<<<1, 32>>>(out, (float)n);
}